// round 1
// baseline (speedup 1.0000x reference)
#include <cuda_runtime.h>
#include <cuda_bf16.h>
#include <math.h>

#define S_LEN 2048
#define E_DIM 1024
#define NH    8
#define DH    128
#define BM    64
#define BN    64
#define EPS_F 1e-6f

// ---------------- scratch (no allocations allowed) ----------------
__device__ float g_pre[16][S_LEN];   // rows 0-7: i_pre per head; 8-15: f_pre per head
__device__ float g_a  [NH][S_LEN];   // a[j] = i_pre[j] - cum[j]
__device__ float g_M  [NH][S_LEN];   // prefix max of a
__device__ float g_n2 [NH][S_LEN];   // exp(-(cum+M)) = exp(-max_log_D)

// =================================================================
// Kernel 1: gate preactivations  i_pre/f_pre = [q|k|v] @ W + b
// grid 128 blocks x 256 threads; W (3072x16) staged in 196KB smem.
// Each block handles 16 s-rows in 4 passes of 4 rows.
// =================================================================
__global__ void gate_kernel(const float* __restrict__ q,
                            const float* __restrict__ k,
                            const float* __restrict__ v,
                            const float* __restrict__ Wi,
                            const float* __restrict__ bi,
                            const float* __restrict__ Wf,
                            const float* __restrict__ bf) {
    extern __shared__ float sW[];           // [3072][16]
    __shared__ float red[8][64];
    int tid = threadIdx.x;

    for (int idx = tid; idx < 3072 * 8; idx += 256) {
        int e = idx >> 3, hh = idx & 7;
        sW[e * 16 + hh]     = Wi[idx];
        sW[e * 16 + 8 + hh] = Wf[idx];
    }
    __syncthreads();

    int s0 = blockIdx.x * 16;
    for (int pass = 0; pass < 4; ++pass) {
        int s = s0 + pass * 4;
        float acc[4][16];
        #pragma unroll
        for (int r = 0; r < 4; ++r)
            #pragma unroll
            for (int g = 0; g < 16; ++g) acc[r][g] = 0.f;

        #pragma unroll
        for (int j = 0; j < 12; ++j) {
            int e = tid + j * 256;
            const float* x = (j < 4) ? q : (j < 8) ? k : v;
            int col = e & 1023;
            float xv[4];
            #pragma unroll
            for (int r = 0; r < 4; ++r) xv[r] = x[(s + r) * E_DIM + col];
            const float4 w0 = *(const float4*)&sW[e * 16 + 0];
            const float4 w1 = *(const float4*)&sW[e * 16 + 4];
            const float4 w2 = *(const float4*)&sW[e * 16 + 8];
            const float4 w3 = *(const float4*)&sW[e * 16 + 12];
            #pragma unroll
            for (int r = 0; r < 4; ++r) {
                acc[r][0]  += xv[r] * w0.x;  acc[r][1]  += xv[r] * w0.y;
                acc[r][2]  += xv[r] * w0.z;  acc[r][3]  += xv[r] * w0.w;
                acc[r][4]  += xv[r] * w1.x;  acc[r][5]  += xv[r] * w1.y;
                acc[r][6]  += xv[r] * w1.z;  acc[r][7]  += xv[r] * w1.w;
                acc[r][8]  += xv[r] * w2.x;  acc[r][9]  += xv[r] * w2.y;
                acc[r][10] += xv[r] * w2.z;  acc[r][11] += xv[r] * w2.w;
                acc[r][12] += xv[r] * w3.x;  acc[r][13] += xv[r] * w3.y;
                acc[r][14] += xv[r] * w3.z;  acc[r][15] += xv[r] * w3.w;
            }
        }
        // warp reduce
        #pragma unroll
        for (int off = 16; off > 0; off >>= 1)
            #pragma unroll
            for (int r = 0; r < 4; ++r)
                #pragma unroll
                for (int g = 0; g < 16; ++g)
                    acc[r][g] += __shfl_down_sync(0xffffffffu, acc[r][g], off);
        int wid = tid >> 5, lane = tid & 31;
        if (lane == 0) {
            #pragma unroll
            for (int r = 0; r < 4; ++r)
                #pragma unroll
                for (int g = 0; g < 16; ++g)
                    red[wid][r * 16 + g] = acc[r][g];
        }
        __syncthreads();
        if (tid < 64) {
            float sum = 0.f;
            #pragma unroll
            for (int w = 0; w < 8; ++w) sum += red[w][tid];
            int r = tid >> 4, g = tid & 15;
            int srow = s + r;
            float b = (g < 8) ? bi[g] : bf[g - 8];
            g_pre[g][srow] = sum + b;
        }
        __syncthreads();
    }
}

// =================================================================
// Kernel 2: per-head scans. 8 blocks x 1024 threads (2 elems each).
// cumsum(log_sigmoid(f)), a = i_pre - cum, M = prefixmax(a),
// n2 = exp(-(cum+M)).
// =================================================================
__device__ __forceinline__ float lsig(float x) {
    float m = fminf(x, 0.f);
    return m - log1pf(expf(-fabsf(x)));
}

__global__ void scan_kernel() {
    int h = blockIdx.x;
    int t = threadIdx.x;               // 0..1023
    __shared__ float sc[1024];
    __shared__ float sm[1024];

    float f0 = g_pre[8 + h][2 * t];
    float f1 = g_pre[8 + h][2 * t + 1];
    float l0 = lsig(f0), l1 = lsig(f1);

    sc[t] = l0 + l1;
    __syncthreads();
    for (int off = 1; off < 1024; off <<= 1) {
        float vv = (t >= off) ? sc[t - off] : 0.f;
        __syncthreads();
        sc[t] += vv;
        __syncthreads();
    }
    float excl = (t > 0) ? sc[t - 1] : 0.f;
    float cum0 = excl + l0;
    float cum1 = cum0 + l1;

    float ip0 = g_pre[h][2 * t];
    float ip1 = g_pre[h][2 * t + 1];
    float a0 = ip0 - cum0;
    float a1 = ip1 - cum1;
    g_a[h][2 * t]     = a0;
    g_a[h][2 * t + 1] = a1;

    sm[t] = fmaxf(a0, a1);
    __syncthreads();
    for (int off = 1; off < 1024; off <<= 1) {
        float vv = (t >= off) ? sm[t - off] : -3.4e38f;
        __syncthreads();
        sm[t] = fmaxf(sm[t], vv);
        __syncthreads();
    }
    float exm = (t > 0) ? sm[t - 1] : -3.4e38f;
    float M0 = fmaxf(exm, a0);
    float M1 = fmaxf(M0, a1);
    g_M[h][2 * t]     = M0;
    g_M[h][2 * t + 1] = M1;
    g_n2[h][2 * t]     = expf(-(cum0 + M0));
    g_n2[h][2 * t + 1] = expf(-(cum1 + M1));
}

// =================================================================
// Kernel 3: causal decayed attention + normalizer + per-head LN.
// grid (32, 8), 256 threads, ~121.6 KB dynamic smem, fp32.
// Thread map: ty=tid/16 owns 4 rows, tx=tid%16 owns 4 S-cols / 8 O-cols.
// =================================================================
__global__ void attn_kernel(const float* __restrict__ q,
                            const float* __restrict__ k,
                            const float* __restrict__ v,
                            const float* __restrict__ lnsc,
                            float* __restrict__ out) {
    extern __shared__ float smem[];
    float* Qt  = smem;                 // [128][68]
    float* Kt  = Qt + 128 * 68;        // [128][68]
    float* Vs  = Kt + 128 * 68;        // [64][132]
    float* Ps  = Vs + 64 * 132;        // [64][68]
    float* sa  = Ps + 64 * 68;         // [64]
    float* sM  = sa + 64;              // [64]
    float* sn2 = sM + 64;              // [64]

    int h  = blockIdx.y;
    int qt = (gridDim.x - 1) - blockIdx.x;   // heavy tiles first
    int i0 = qt * BM;
    int tid = threadIdx.x;
    int ty = tid >> 4, tx = tid & 15;

    const float inv = 0.08838834764831845f;  // 1/sqrt(128)

    // load Q^T (scaled) and row stats
    for (int idx = tid; idx < BM * DH / 4; idx += 256) {
        int ii = idx >> 5, kq = (idx & 31) * 4;
        float4 t4 = *(const float4*)&q[(i0 + ii) * E_DIM + h * DH + kq];
        Qt[(kq + 0) * 68 + ii] = t4.x * inv;
        Qt[(kq + 1) * 68 + ii] = t4.y * inv;
        Qt[(kq + 2) * 68 + ii] = t4.z * inv;
        Qt[(kq + 3) * 68 + ii] = t4.w * inv;
    }
    if (tid < 64) {
        sM[tid]  = g_M[h][i0 + tid];
        sn2[tid] = g_n2[h][i0 + tid];
    }
    float oacc[4][8];
    #pragma unroll
    for (int a = 0; a < 4; ++a)
        #pragma unroll
        for (int c = 0; c < 8; ++c) oacc[a][c] = 0.f;
    float rs[4] = {0.f, 0.f, 0.f, 0.f};
    __syncthreads();
    float Mrow[4];
    #pragma unroll
    for (int a = 0; a < 4; ++a) Mrow[a] = sM[ty * 4 + a];

    for (int j0 = 0; j0 <= i0; j0 += BN) {
        __syncthreads();  // previous PV reads done before overwrite
        for (int idx = tid; idx < BN * DH / 4; idx += 256) {
            int jj = idx >> 5, kq = (idx & 31) * 4;
            float4 kt4 = *(const float4*)&k[(j0 + jj) * E_DIM + h * DH + kq];
            Kt[(kq + 0) * 68 + jj] = kt4.x;
            Kt[(kq + 1) * 68 + jj] = kt4.y;
            Kt[(kq + 2) * 68 + jj] = kt4.z;
            Kt[(kq + 3) * 68 + jj] = kt4.w;
            float4 vt4 = *(const float4*)&v[(j0 + jj) * E_DIM + h * DH + kq];
            *(float4*)&Vs[jj * 132 + kq] = vt4;
        }
        if (tid < 64) sa[tid] = g_a[h][j0 + tid];
        __syncthreads();

        // ---- QK^T: 4x4 fragment per thread ----
        float acc[4][4];
        #pragma unroll
        for (int a = 0; a < 4; ++a)
            #pragma unroll
            for (int b = 0; b < 4; ++b) acc[a][b] = 0.f;
        #pragma unroll 4
        for (int kd = 0; kd < DH; ++kd) {
            float4 qf = *(const float4*)&Qt[kd * 68 + ty * 4];
            float4 kf = *(const float4*)&Kt[kd * 68 + tx * 4];
            acc[0][0] += qf.x * kf.x; acc[0][1] += qf.x * kf.y;
            acc[0][2] += qf.x * kf.z; acc[0][3] += qf.x * kf.w;
            acc[1][0] += qf.y * kf.x; acc[1][1] += qf.y * kf.y;
            acc[1][2] += qf.y * kf.z; acc[1][3] += qf.y * kf.w;
            acc[2][0] += qf.z * kf.x; acc[2][1] += qf.z * kf.y;
            acc[2][2] += qf.z * kf.z; acc[2][3] += qf.z * kf.w;
            acc[3][0] += qf.w * kf.x; acc[3][1] += qf.w * kf.y;
            acc[3][2] += qf.w * kf.z; acc[3][3] += qf.w * kf.w;
        }

        // ---- decay weights + causal mask + rowsum, stage P to smem ----
        bool diag = (j0 == i0);
        #pragma unroll
        for (int a = 0; a < 4; ++a) {
            int ii = ty * 4 + a;
            #pragma unroll
            for (int b = 0; b < 4; ++b) {
                int jj = tx * 4 + b;
                float w = acc[a][b] * __expf(sa[jj] - Mrow[a]);
                if (diag && (jj > ii)) w = 0.f;
                rs[a] += w;
                Ps[ii * 68 + jj] = w;
            }
        }
        __syncthreads();

        // ---- P @ V: 4 rows x 8 cols per thread ----
        #pragma unroll 2
        for (int j = 0; j < BN; ++j) {
            float4 v0 = *(const float4*)&Vs[j * 132 + tx * 8];
            float4 v1 = *(const float4*)&Vs[j * 132 + tx * 8 + 4];
            #pragma unroll
            for (int a = 0; a < 4; ++a) {
                float pr = Ps[(ty * 4 + a) * 68 + j];
                oacc[a][0] += pr * v0.x; oacc[a][1] += pr * v0.y;
                oacc[a][2] += pr * v0.z; oacc[a][3] += pr * v0.w;
                oacc[a][4] += pr * v1.x; oacc[a][5] += pr * v1.y;
                oacc[a][6] += pr * v1.z; oacc[a][7] += pr * v1.w;
            }
        }
    }

    // ---- epilogue: normalizer + per-head LayerNorm ----
    float4 g0 = *(const float4*)&lnsc[h * DH + tx * 8];
    float4 g1 = *(const float4*)&lnsc[h * DH + tx * 8 + 4];
    #pragma unroll
    for (int a = 0; a < 4; ++a) {
        float r = rs[a];
        r += __shfl_xor_sync(0xffffffffu, r, 1);
        r += __shfl_xor_sync(0xffffffffu, r, 2);
        r += __shfl_xor_sync(0xffffffffu, r, 4);
        r += __shfl_xor_sync(0xffffffffu, r, 8);
        float denom = fmaxf(fabsf(r), sn2[ty * 4 + a]) + EPS_F;
        float invd = 1.f / denom;

        float lsum = 0.f, lsq = 0.f;
        #pragma unroll
        for (int c = 0; c < 8; ++c) {
            float x = oacc[a][c] * invd;
            oacc[a][c] = x;
            lsum += x;
            lsq  += x * x;
        }
        lsum += __shfl_xor_sync(0xffffffffu, lsum, 1);
        lsum += __shfl_xor_sync(0xffffffffu, lsum, 2);
        lsum += __shfl_xor_sync(0xffffffffu, lsum, 4);
        lsum += __shfl_xor_sync(0xffffffffu, lsum, 8);
        lsq  += __shfl_xor_sync(0xffffffffu, lsq, 1);
        lsq  += __shfl_xor_sync(0xffffffffu, lsq, 2);
        lsq  += __shfl_xor_sync(0xffffffffu, lsq, 4);
        lsq  += __shfl_xor_sync(0xffffffffu, lsq, 8);
        float mean = lsum * (1.f / 128.f);
        float varr = lsq * (1.f / 128.f) - mean * mean;
        float rstd = rsqrtf(varr + EPS_F);

        int row = i0 + ty * 4 + a;
        float4 o0, o1;
        o0.x = (oacc[a][0] - mean) * rstd * g0.x;
        o0.y = (oacc[a][1] - mean) * rstd * g0.y;
        o0.z = (oacc[a][2] - mean) * rstd * g0.z;
        o0.w = (oacc[a][3] - mean) * rstd * g0.w;
        o1.x = (oacc[a][4] - mean) * rstd * g1.x;
        o1.y = (oacc[a][5] - mean) * rstd * g1.y;
        o1.z = (oacc[a][6] - mean) * rstd * g1.z;
        o1.w = (oacc[a][7] - mean) * rstd * g1.w;
        *(float4*)&out[row * E_DIM + h * DH + tx * 8]     = o0;
        *(float4*)&out[row * E_DIM + h * DH + tx * 8 + 4] = o1;
    }
}

// =================================================================
extern "C" void kernel_launch(void* const* d_in, const int* in_sizes, int n_in,
                              void* d_out, int out_size) {
    const float* q    = (const float*)d_in[0];
    const float* k    = (const float*)d_in[1];
    const float* v    = (const float*)d_in[2];
    const float* Wi   = (const float*)d_in[3];
    const float* bi   = (const float*)d_in[4];
    const float* Wf   = (const float*)d_in[5];
    const float* bf   = (const float*)d_in[6];
    const float* lnsc = (const float*)d_in[7];
    float* out = (float*)d_out;

    const int gate_smem = 3072 * 16 * 4;                  // 196608 B
    const int attn_smem = (128*68 + 128*68 + 64*132 + 64*68 + 192) * 4;  // 121600 B

    cudaFuncSetAttribute(gate_kernel, cudaFuncAttributeMaxDynamicSharedMemorySize, gate_smem);
    cudaFuncSetAttribute(attn_kernel, cudaFuncAttributeMaxDynamicSharedMemorySize, attn_smem);

    gate_kernel<<<128, 256, gate_smem>>>(q, k, v, Wi, bi, Wf, bf);
    scan_kernel<<<8, 1024>>>();
    dim3 grid(S_LEN / BM, NH);
    attn_kernel<<<grid, 256, attn_smem>>>(q, k, v, lnsc, out);
}

// round 2
// speedup vs baseline: 5.2203x; 5.2203x over previous
#include <cuda_runtime.h>
#include <math.h>

#define S_LEN 2048
#define E_DIM 1024
#define NH    8
#define DH    128
#define EPS_F 1e-6f

// ---------------- scratch ----------------
__device__ float g_pre[16][S_LEN];   // 0-7: i_pre per head; 8-15: f_pre
__device__ float g_M [NH][S_LEN];    // prefix max of a[j] = i_pre - cum
__device__ float g_n2[NH][S_LEN];    // exp(-(cum+M)) = exp(-max_log_D)
__device__ float g_E [NH][S_LEN];    // exp(a[j] - T_tile(j))
__device__ float g_T [NH][S_LEN/128];// per-128-tile max of a

__device__ __forceinline__ float tf32r(float x) {
    unsigned r;
    asm("cvt.rna.tf32.f32 %0, %1;" : "=r"(r) : "f"(x));
    return __uint_as_float(r);
}
__device__ __forceinline__ void mma8(float* d, const unsigned* a, const unsigned* b) {
    asm volatile("mma.sync.aligned.m16n8k8.row.col.f32.tf32.tf32.f32 "
        "{%0,%1,%2,%3}, {%4,%5,%6,%7}, {%8,%9}, {%0,%1,%2,%3};"
        : "+f"(d[0]), "+f"(d[1]), "+f"(d[2]), "+f"(d[3])
        : "r"(a[0]), "r"(a[1]), "r"(a[2]), "r"(a[3]), "r"(b[0]), "r"(b[1]));
}

// =================================================================
// Kernel 1: gate preactivations. W staged [3072][18] (pad -> no conflicts)
// =================================================================
__global__ void gate_kernel(const float* __restrict__ q,
                            const float* __restrict__ k,
                            const float* __restrict__ v,
                            const float* __restrict__ Wi,
                            const float* __restrict__ bi,
                            const float* __restrict__ Wf,
                            const float* __restrict__ bf) {
    extern __shared__ float sW[];           // [3072][18]
    __shared__ float red[8][64];
    int tid = threadIdx.x;

    for (int idx = tid; idx < 3072 * 8; idx += 256) {
        int e = idx >> 3, hh = idx & 7;
        sW[e * 18 + hh]     = Wi[idx];
        sW[e * 18 + 8 + hh] = Wf[idx];
    }
    __syncthreads();

    int s0 = blockIdx.x * 16;
    for (int pass = 0; pass < 4; ++pass) {
        int s = s0 + pass * 4;
        float acc[4][16];
        #pragma unroll
        for (int r = 0; r < 4; ++r)
            #pragma unroll
            for (int g = 0; g < 16; ++g) acc[r][g] = 0.f;

        #pragma unroll
        for (int j = 0; j < 12; ++j) {
            int e = tid + j * 256;
            const float* x = (j < 4) ? q : (j < 8) ? k : v;
            int col = e & 1023;
            float xv[4];
            #pragma unroll
            for (int r = 0; r < 4; ++r) xv[r] = x[(s + r) * E_DIM + col];
            float2 wp[8];
            #pragma unroll
            for (int p = 0; p < 8; ++p) wp[p] = *(const float2*)&sW[e * 18 + 2 * p];
            #pragma unroll
            for (int r = 0; r < 4; ++r)
                #pragma unroll
                for (int p = 0; p < 8; ++p) {
                    acc[r][2 * p]     += xv[r] * wp[p].x;
                    acc[r][2 * p + 1] += xv[r] * wp[p].y;
                }
        }
        #pragma unroll
        for (int off = 16; off > 0; off >>= 1)
            #pragma unroll
            for (int r = 0; r < 4; ++r)
                #pragma unroll
                for (int g = 0; g < 16; ++g)
                    acc[r][g] += __shfl_down_sync(0xffffffffu, acc[r][g], off);
        int wid = tid >> 5, lane = tid & 31;
        if (lane == 0) {
            #pragma unroll
            for (int r = 0; r < 4; ++r)
                #pragma unroll
                for (int g = 0; g < 16; ++g)
                    red[wid][r * 16 + g] = acc[r][g];
        }
        __syncthreads();
        if (tid < 64) {
            float sum = 0.f;
            #pragma unroll
            for (int w = 0; w < 8; ++w) sum += red[w][tid];
            int r = tid >> 4, g = tid & 15;
            float b = (g < 8) ? bi[g] : bf[g - 8];
            g_pre[g][s + r] = sum + b;
        }
        __syncthreads();
    }
}

// =================================================================
// Kernel 2: scans. cum, a, M, n2, per-128-tile max T, E = exp(a-T).
// =================================================================
__device__ __forceinline__ float lsig(float x) {
    float m = fminf(x, 0.f);
    return m - log1pf(expf(-fabsf(x)));
}

__global__ void scan_kernel() {
    int h = blockIdx.x;
    int t = threadIdx.x;               // 0..1023, elems 2t, 2t+1
    __shared__ float sc[1024];
    __shared__ float sm[1024];
    __shared__ float stmax[32];

    float l0 = lsig(g_pre[8 + h][2 * t]);
    float l1 = lsig(g_pre[8 + h][2 * t + 1]);

    sc[t] = l0 + l1;
    __syncthreads();
    for (int off = 1; off < 1024; off <<= 1) {
        float vv = (t >= off) ? sc[t - off] : 0.f;
        __syncthreads();
        sc[t] += vv;
        __syncthreads();
    }
    float excl = (t > 0) ? sc[t - 1] : 0.f;
    float cum0 = excl + l0;
    float cum1 = cum0 + l1;

    float a0 = g_pre[h][2 * t]     - cum0;
    float a1 = g_pre[h][2 * t + 1] - cum1;

    // prefix max of a
    sm[t] = fmaxf(a0, a1);
    __syncthreads();
    for (int off = 1; off < 1024; off <<= 1) {
        float vv = (t >= off) ? sm[t - off] : -3.4e38f;
        __syncthreads();
        sm[t] = fmaxf(sm[t], vv);
        __syncthreads();
    }
    float exm = (t > 0) ? sm[t - 1] : -3.4e38f;
    float M0 = fmaxf(exm, a0);
    float M1 = fmaxf(M0, a1);
    g_M[h][2 * t]      = M0;
    g_M[h][2 * t + 1]  = M1;
    g_n2[h][2 * t]     = expf(-(cum0 + M0));
    g_n2[h][2 * t + 1] = expf(-(cum1 + M1));

    // per-128-elem tile max (64 threads = 2 warps per tile)
    int w = t >> 5, lane = t & 31;
    float mx = fmaxf(a0, a1);
    #pragma unroll
    for (int off = 16; off > 0; off >>= 1)
        mx = fmaxf(mx, __shfl_xor_sync(0xffffffffu, mx, off));
    if (lane == 0) stmax[w] = mx;
    __syncthreads();
    float T = fmaxf(stmax[w & ~1], stmax[w | 1]);
    if ((w & 1) == 0 && lane == 0) g_T[h][w >> 1] = T;
    g_E[h][2 * t]     = expf(a0 - T);
    g_E[h][2 * t + 1] = expf(a1 - T);
}

// =================================================================
// Kernel 3: tf32 tensor-core flash attention + normalizer + LN.
// BM=64, BN=128, 256 threads, warp grid 2(m) x 4(n), warp tile m32n32.
// CTA processes q-tiles {31-pair, pair} -> exactly 17 j-tile units each.
// =================================================================
__global__ void __launch_bounds__(256, 1)
attn_kernel(const float* __restrict__ q,
            const float* __restrict__ k,
            const float* __restrict__ v,
            const float* __restrict__ lnsc,
            float* __restrict__ out) {
    extern __shared__ float smem[];
    float* Qs  = smem;               // [64][132]
    float* Ks  = Qs + 64 * 132;      // [128][132]
    float* Vs  = Ks + 128 * 132;     // [128][136]
    float* Ps  = Vs + 128 * 136;     // [64][132]
    float* sMq = Ps + 64 * 132;      // [64]
    float* sn2 = sMq + 64;           // [64]
    float* sR  = sn2 + 64;           // [64]
    float* rrs = sR + 64;            // [4][64]
    float* rsm = rrs + 256;          // [4][64]
    float* rsq = rsm + 256;          // [4][64]

    int h    = blockIdx.y;
    int pair = blockIdx.x;
    int tid  = threadIdx.x;
    int wid  = tid >> 5, lane = tid & 31;
    int wy   = wid >> 2, wx = wid & 3;     // wy in 0..1 (m), wx in 0..3 (n)
    int g    = lane >> 2, tig = lane & 3;

    const float qscale = 0.08838834764831845f;   // 1/sqrt(128)

    for (int qsel = 0; qsel < 2; ++qsel) {
        int qt  = qsel ? pair : (31 - pair);     // heavy block first
        int i0  = qt * 64;
        int njt = qt / 2 + 1;

        __syncthreads();  // prior epilogue done before smem reuse
        // load Q (tf32, pre-scaled)
        for (int idx = tid; idx < 64 * 32; idx += 256) {
            int i = idx >> 5, c4 = (idx & 31) * 4;
            float4 t4 = *(const float4*)&q[(i0 + i) * E_DIM + h * DH + c4];
            float4 o4 = make_float4(tf32r(t4.x * qscale), tf32r(t4.y * qscale),
                                    tf32r(t4.z * qscale), tf32r(t4.w * qscale));
            *(float4*)&Qs[i * 132 + c4] = o4;
        }
        if (tid < 64) {
            sMq[tid] = g_M[h][i0 + tid];
            sn2[tid] = g_n2[h][i0 + tid];
        }

        float Oa[2][4][4];
        #pragma unroll
        for (int mi = 0; mi < 2; ++mi)
            #pragma unroll
            for (int nt = 0; nt < 4; ++nt)
                #pragma unroll
                for (int c = 0; c < 4; ++c) Oa[mi][nt][c] = 0.f;
        float rs[2][2] = {{0.f, 0.f}, {0.f, 0.f}};

        for (int jt = 0; jt < njt; ++jt) {
            int j0 = jt * 128;
            __syncthreads();   // prior PV reads done; sMq visible
            float T = g_T[h][jt];
            for (int idx = tid; idx < 128 * 32; idx += 256) {
                int j = idx >> 5, c4 = (idx & 31) * 4;
                float e = g_E[h][j0 + j];
                float4 kt = *(const float4*)&k[(j0 + j) * E_DIM + h * DH + c4];
                float4 ko = make_float4(tf32r(kt.x * e), tf32r(kt.y * e),
                                        tf32r(kt.z * e), tf32r(kt.w * e));
                *(float4*)&Ks[j * 132 + c4] = ko;
                float4 vt = *(const float4*)&v[(j0 + j) * E_DIM + h * DH + c4];
                float4 vo = make_float4(tf32r(vt.x), tf32r(vt.y),
                                        tf32r(vt.z), tf32r(vt.w));
                *(float4*)&Vs[j * 136 + c4] = vo;
            }
            if (tid < 64) sR[tid] = __expf(T - sMq[tid]);
            __syncthreads();

            // ---- QK^T (tf32 mma), warp tile m32 x n32 ----
            float acc[2][4][4];
            #pragma unroll
            for (int mi = 0; mi < 2; ++mi)
                #pragma unroll
                for (int nt = 0; nt < 4; ++nt)
                    #pragma unroll
                    for (int c = 0; c < 4; ++c) acc[mi][nt][c] = 0.f;

            #pragma unroll
            for (int ks = 0; ks < 16; ++ks) {
                int d0 = ks * 8;
                unsigned a[2][4], b[4][2];
                #pragma unroll
                for (int mi = 0; mi < 2; ++mi) {
                    int r0 = wy * 32 + mi * 16 + g;
                    a[mi][0] = __float_as_uint(Qs[r0 * 132 + d0 + tig]);
                    a[mi][1] = __float_as_uint(Qs[(r0 + 8) * 132 + d0 + tig]);
                    a[mi][2] = __float_as_uint(Qs[r0 * 132 + d0 + tig + 4]);
                    a[mi][3] = __float_as_uint(Qs[(r0 + 8) * 132 + d0 + tig + 4]);
                }
                #pragma unroll
                for (int nt = 0; nt < 4; ++nt) {
                    int jb = wx * 32 + nt * 8 + g;
                    b[nt][0] = __float_as_uint(Ks[jb * 132 + d0 + tig]);
                    b[nt][1] = __float_as_uint(Ks[jb * 132 + d0 + tig + 4]);
                }
                #pragma unroll
                for (int mi = 0; mi < 2; ++mi)
                    #pragma unroll
                    for (int nt = 0; nt < 4; ++nt)
                        mma8(acc[mi][nt], a[mi], b[nt]);
            }

            // ---- apply R, mask, rowsum, stage P ----
            bool last = (jt == njt - 1);
            #pragma unroll
            for (int mi = 0; mi < 2; ++mi) {
                int rl = wy * 32 + mi * 16 + g;
                float Rl = sR[rl], Rh = sR[rl + 8];
                int iglo = i0 + rl, ighi = iglo + 8;
                #pragma unroll
                for (int nt = 0; nt < 4; ++nt) {
                    int jc = wx * 32 + nt * 8 + 2 * tig;
                    int jg = j0 + jc;
                    float p0 = acc[mi][nt][0] * Rl;
                    float p1 = acc[mi][nt][1] * Rl;
                    float p2 = acc[mi][nt][2] * Rh;
                    float p3 = acc[mi][nt][3] * Rh;
                    if (last) {
                        if (jg     > iglo) p0 = 0.f;
                        if (jg + 1 > iglo) p1 = 0.f;
                        if (jg     > ighi) p2 = 0.f;
                        if (jg + 1 > ighi) p3 = 0.f;
                    }
                    rs[mi][0] += p0 + p1;
                    rs[mi][1] += p2 + p3;
                    *(float2*)&Ps[rl * 132 + jc]       = make_float2(tf32r(p0), tf32r(p1));
                    *(float2*)&Ps[(rl + 8) * 132 + jc] = make_float2(tf32r(p2), tf32r(p3));
                }
            }
            __syncthreads();

            // ---- P @ V (tf32 mma) ----
            #pragma unroll
            for (int ks = 0; ks < 16; ++ks) {
                int j8 = ks * 8;
                unsigned a[2][4], b[4][2];
                #pragma unroll
                for (int mi = 0; mi < 2; ++mi) {
                    int r0 = wy * 32 + mi * 16 + g;
                    a[mi][0] = __float_as_uint(Ps[r0 * 132 + j8 + tig]);
                    a[mi][1] = __float_as_uint(Ps[(r0 + 8) * 132 + j8 + tig]);
                    a[mi][2] = __float_as_uint(Ps[r0 * 132 + j8 + tig + 4]);
                    a[mi][3] = __float_as_uint(Ps[(r0 + 8) * 132 + j8 + tig + 4]);
                }
                #pragma unroll
                for (int nt = 0; nt < 4; ++nt) {
                    int d = wx * 32 + nt * 8 + g;
                    b[nt][0] = __float_as_uint(Vs[(j8 + tig) * 136 + d]);
                    b[nt][1] = __float_as_uint(Vs[(j8 + tig + 4) * 136 + d]);
                }
                #pragma unroll
                for (int mi = 0; mi < 2; ++mi)
                    #pragma unroll
                    for (int nt = 0; nt < 4; ++nt)
                        mma8(Oa[mi][nt], a[mi], b[nt]);
            }
        }

        // ---- epilogue: reduce rs / sum / sumsq, normalize, LN, store ----
        float sm1[2][2] = {{0.f,0.f},{0.f,0.f}};
        float sq1[2][2] = {{0.f,0.f},{0.f,0.f}};
        #pragma unroll
        for (int mi = 0; mi < 2; ++mi)
            #pragma unroll
            for (int nt = 0; nt < 4; ++nt) {
                sm1[mi][0] += Oa[mi][nt][0] + Oa[mi][nt][1];
                sq1[mi][0] += Oa[mi][nt][0] * Oa[mi][nt][0] + Oa[mi][nt][1] * Oa[mi][nt][1];
                sm1[mi][1] += Oa[mi][nt][2] + Oa[mi][nt][3];
                sq1[mi][1] += Oa[mi][nt][2] * Oa[mi][nt][2] + Oa[mi][nt][3] * Oa[mi][nt][3];
            }
        #pragma unroll
        for (int mi = 0; mi < 2; ++mi)
            #pragma unroll
            for (int c = 0; c < 2; ++c) {
                rs [mi][c] += __shfl_xor_sync(0xffffffffu, rs [mi][c], 1);
                rs [mi][c] += __shfl_xor_sync(0xffffffffu, rs [mi][c], 2);
                sm1[mi][c] += __shfl_xor_sync(0xffffffffu, sm1[mi][c], 1);
                sm1[mi][c] += __shfl_xor_sync(0xffffffffu, sm1[mi][c], 2);
                sq1[mi][c] += __shfl_xor_sync(0xffffffffu, sq1[mi][c], 1);
                sq1[mi][c] += __shfl_xor_sync(0xffffffffu, sq1[mi][c], 2);
            }
        if (tig == 0) {
            #pragma unroll
            for (int mi = 0; mi < 2; ++mi)
                #pragma unroll
                for (int c = 0; c < 2; ++c) {
                    int row = wy * 32 + mi * 16 + g + 8 * c;
                    rrs[wx * 64 + row] = rs [mi][c];
                    rsm[wx * 64 + row] = sm1[mi][c];
                    rsq[wx * 64 + row] = sq1[mi][c];
                }
        }
        __syncthreads();
        if (tid < 64) {
            float tot = rrs[tid] + rrs[64 + tid] + rrs[128 + tid] + rrs[192 + tid];
            float s1  = rsm[tid] + rsm[64 + tid] + rsm[128 + tid] + rsm[192 + tid];
            float s2  = rsq[tid] + rsq[64 + tid] + rsq[128 + tid] + rsq[192 + tid];
            float denom = fmaxf(fabsf(tot), sn2[tid]) + EPS_F;
            float invd  = 1.f / denom;
            float mean  = s1 * invd * (1.f / 128.f);
            float ex2   = s2 * invd * invd * (1.f / 128.f);
            float rstd  = rsqrtf(ex2 - mean * mean + EPS_F);
            sR [tid] = invd;
            sMq[tid] = mean;
            sn2[tid] = rstd;
        }
        __syncthreads();
        float2 gp[4];
        #pragma unroll
        for (int nt = 0; nt < 4; ++nt)
            gp[nt] = *(const float2*)&lnsc[h * DH + wx * 32 + nt * 8 + 2 * tig];
        #pragma unroll
        for (int mi = 0; mi < 2; ++mi)
            #pragma unroll
            for (int c = 0; c < 2; ++c) {
                int row = wy * 32 + mi * 16 + g + 8 * c;
                float invd = sR[row], mean = sMq[row], rstd = sn2[row];
                int grow = i0 + row;
                #pragma unroll
                for (int nt = 0; nt < 4; ++nt) {
                    float x0 = (Oa[mi][nt][2 * c]     * invd - mean) * rstd * gp[nt].x;
                    float x1 = (Oa[mi][nt][2 * c + 1] * invd - mean) * rstd * gp[nt].y;
                    *(float2*)&out[grow * E_DIM + h * DH + wx * 32 + nt * 8 + 2 * tig]
                        = make_float2(x0, x1);
                }
            }
    }
}

// =================================================================
extern "C" void kernel_launch(void* const* d_in, const int* in_sizes, int n_in,
                              void* d_out, int out_size) {
    const float* q    = (const float*)d_in[0];
    const float* k    = (const float*)d_in[1];
    const float* v    = (const float*)d_in[2];
    const float* Wi   = (const float*)d_in[3];
    const float* bi   = (const float*)d_in[4];
    const float* Wf   = (const float*)d_in[5];
    const float* bf   = (const float*)d_in[6];
    const float* lnsc = (const float*)d_in[7];
    float* out = (float*)d_out;

    const int gate_smem = 3072 * 18 * 4;                            // 221184 B
    const int attn_smem = (64*132 + 128*132 + 128*136 + 64*132 + 64*3 + 256*3) * 4; // 208640 B

    cudaFuncSetAttribute(gate_kernel, cudaFuncAttributeMaxDynamicSharedMemorySize, gate_smem);
    cudaFuncSetAttribute(attn_kernel, cudaFuncAttributeMaxDynamicSharedMemorySize, attn_smem);

    gate_kernel<<<128, 256, gate_smem>>>(q, k, v, Wi, bi, Wf, bf);
    scan_kernel<<<8, 1024>>>();
    dim3 grid(16, NH);
    attn_kernel<<<grid, 256, attn_smem>>>(q, k, v, lnsc, out);
}

// round 3
// speedup vs baseline: 6.3937x; 1.2248x over previous
#include <cuda_runtime.h>
#include <cuda_fp16.h>
#include <math.h>

#define S_LEN 2048
#define E_DIM 1024
#define NH    8
#define DH    128
#define EPS_F 1e-6f

// ---------------- scratch ----------------
__device__ float g_part[3][16][S_LEN];  // gate partials: slice, gate(0-7 i, 8-15 f), s
__device__ float g_M [NH][S_LEN];       // prefix max of a[j] = i_pre - cum
__device__ float g_n2[NH][S_LEN];       // exp(-(cum+M)) = exp(-max_log_D)
__device__ float g_E [NH][S_LEN];       // exp(a[j] - T_tile(j))
__device__ float g_T [NH][S_LEN/128];   // per-128-tile max of a

__device__ __forceinline__ void mma16(float* d, const unsigned* a, const unsigned* b) {
    asm volatile("mma.sync.aligned.m16n8k16.row.col.f32.f16.f16.f32 "
        "{%0,%1,%2,%3}, {%4,%5,%6,%7}, {%8,%9}, {%0,%1,%2,%3};"
        : "+f"(d[0]), "+f"(d[1]), "+f"(d[2]), "+f"(d[3])
        : "r"(a[0]), "r"(a[1]), "r"(a[2]), "r"(a[3]), "r"(b[0]), "r"(b[1]));
}
__device__ __forceinline__ void ldsm4t(unsigned* r, unsigned addr) {
    asm volatile("ldmatrix.sync.aligned.m8n8.x4.trans.shared.b16 {%0,%1,%2,%3}, [%4];"
        : "=r"(r[0]), "=r"(r[1]), "=r"(r[2]), "=r"(r[3]) : "r"(addr));
}

// =================================================================
// Kernel 1: gate partials, split-K over 3 slices (q,k,v).
// grid (128,3) x 256 thr; W slice [1024][18] smem (74KB) -> 3 CTA/SM.
// =================================================================
__global__ void gate_kernel(const float* __restrict__ q,
                            const float* __restrict__ k,
                            const float* __restrict__ v,
                            const float* __restrict__ Wi,
                            const float* __restrict__ Wf) {
    extern __shared__ float sW[];          // [1024][18]
    __shared__ float red[8][64];
    int tid = threadIdx.x;
    int sl  = blockIdx.y;
    const float* x = (sl == 0) ? q : (sl == 1) ? k : v;
    int e0 = sl * 1024;

    for (int i = tid; i < 1024 * 8; i += 256) {
        int c = i >> 3, g = i & 7;
        sW[c * 18 + g]     = Wi[(e0 + c) * 8 + g];
        sW[c * 18 + 8 + g] = Wf[(e0 + c) * 8 + g];
    }
    __syncthreads();

    int s0 = blockIdx.x * 16;
    for (int pass = 0; pass < 4; ++pass) {
        int s = s0 + pass * 4;
        float acc[4][16];
        #pragma unroll
        for (int r = 0; r < 4; ++r)
            #pragma unroll
            for (int g = 0; g < 16; ++g) acc[r][g] = 0.f;

        #pragma unroll
        for (int cc = 0; cc < 4; ++cc) {
            int col = tid + cc * 256;
            float xv[4];
            #pragma unroll
            for (int r = 0; r < 4; ++r) xv[r] = x[(s + r) * E_DIM + col];
            float2 wp[8];
            #pragma unroll
            for (int p = 0; p < 8; ++p) wp[p] = *(const float2*)&sW[col * 18 + 2 * p];
            #pragma unroll
            for (int r = 0; r < 4; ++r)
                #pragma unroll
                for (int p = 0; p < 8; ++p) {
                    acc[r][2 * p]     += xv[r] * wp[p].x;
                    acc[r][2 * p + 1] += xv[r] * wp[p].y;
                }
        }
        #pragma unroll
        for (int off = 16; off > 0; off >>= 1)
            #pragma unroll
            for (int r = 0; r < 4; ++r)
                #pragma unroll
                for (int g = 0; g < 16; ++g)
                    acc[r][g] += __shfl_down_sync(0xffffffffu, acc[r][g], off);
        int wid = tid >> 5, lane = tid & 31;
        if (lane == 0) {
            #pragma unroll
            for (int r = 0; r < 4; ++r)
                #pragma unroll
                for (int g = 0; g < 16; ++g)
                    red[wid][r * 16 + g] = acc[r][g];
        }
        __syncthreads();
        if (tid < 64) {
            float sum = 0.f;
            #pragma unroll
            for (int w = 0; w < 8; ++w) sum += red[w][tid];
            int r = tid >> 4, g = tid & 15;
            g_part[sl][g][s + r] = sum;
        }
        __syncthreads();
    }
}

// =================================================================
// Kernel 2: reduce partials + bias, shuffle scans (sum, prefix-max),
// tile max T, E = exp(a-T). 8 blocks x 1024 threads (2 elems each).
// =================================================================
__device__ __forceinline__ float lsig(float x) {
    float m = fminf(x, 0.f);
    return m - log1pf(expf(-fabsf(x)));
}

__global__ void scan_kernel(const float* __restrict__ bi_p,
                            const float* __restrict__ bf_p) {
    int h = blockIdx.x;
    int t = threadIdx.x;
    int lane = t & 31, wid = t >> 5;
    __shared__ float wsum[32], wmax[32], tmax[32];

    float bi = bi_p[h], bf = bf_p[h];
    float i0 = bi, i1 = bi, f0 = bf, f1 = bf;
    #pragma unroll
    for (int sl = 0; sl < 3; ++sl) {
        float2 vi = *(const float2*)&g_part[sl][h][2 * t];
        float2 vf = *(const float2*)&g_part[sl][h + 8][2 * t];
        i0 += vi.x; i1 += vi.y; f0 += vf.x; f1 += vf.y;
    }
    float l0 = lsig(f0), l1 = lsig(f1);

    // inclusive sum scan of pair sums
    float ps = l0 + l1;
    float inc = ps;
    #pragma unroll
    for (int o = 1; o < 32; o <<= 1) {
        float n = __shfl_up_sync(0xffffffffu, inc, o);
        if (lane >= o) inc += n;
    }
    if (lane == 31) wsum[wid] = inc;
    __syncthreads();
    if (t < 32) {
        float v2 = wsum[t];
        #pragma unroll
        for (int o = 1; o < 32; o <<= 1) {
            float n = __shfl_up_sync(0xffffffffu, v2, o);
            if (t >= o) v2 += n;
        }
        wsum[t] = v2;
    }
    __syncthreads();
    float base = wid ? wsum[wid - 1] : 0.f;
    float cum1 = base + inc;
    float cum0 = cum1 - l1;

    float a0 = i0 - cum0, a1 = i1 - cum1;

    // inclusive max scan of pair maxes
    float pm = fmaxf(a0, a1);
    float incm = pm;
    #pragma unroll
    for (int o = 1; o < 32; o <<= 1) {
        float n = __shfl_up_sync(0xffffffffu, incm, o);
        if (lane >= o) incm = fmaxf(incm, n);
    }
    if (lane == 31) wmax[wid] = incm;
    __syncthreads();
    if (t < 32) {
        float v2 = wmax[t];
        #pragma unroll
        for (int o = 1; o < 32; o <<= 1) {
            float n = __shfl_up_sync(0xffffffffu, v2, o);
            if (t >= o) v2 = fmaxf(v2, n);
        }
        wmax[t] = v2;
    }
    __syncthreads();
    float basem = wid ? wmax[wid - 1] : -3.4e38f;
    float prev  = __shfl_up_sync(0xffffffffu, incm, 1);
    float exw   = lane ? prev : -3.4e38f;
    float M0 = fmaxf(fmaxf(basem, exw), a0);
    float M1 = fmaxf(M0, a1);
    g_M[h][2 * t]      = M0;
    g_M[h][2 * t + 1]  = M1;
    g_n2[h][2 * t]     = expf(-(cum0 + M0));
    g_n2[h][2 * t + 1] = expf(-(cum1 + M1));

    // per-128-elem tile max (2 warps per tile)
    float mx = pm;
    #pragma unroll
    for (int off = 16; off > 0; off >>= 1)
        mx = fmaxf(mx, __shfl_xor_sync(0xffffffffu, mx, off));
    if (lane == 0) tmax[wid] = mx;
    __syncthreads();
    float T = fmaxf(tmax[wid & ~1], tmax[wid | 1]);
    if ((wid & 1) == 0 && lane == 0) g_T[h][wid >> 1] = T;
    g_E[h][2 * t]     = expf(a0 - T);
    g_E[h][2 * t + 1] = expf(a1 - T);
}

// =================================================================
// Kernel 3: fp16 tensor-core flash attention + normalizer + LN.
// BM=64, BN=128, 256 thr, warp grid 2(m) x 4(n), warp tile m32n32.
// m16n8k16 f16 mma, fp32 accum. ldmatrix.trans for V B-fragments.
// =================================================================
#define STH 136   // half stride (==8 mod 64 -> conflict-free + ldmatrix-safe)

__global__ void __launch_bounds__(256, 1)
attn_kernel(const float* __restrict__ q,
            const float* __restrict__ k,
            const float* __restrict__ v,
            const float* __restrict__ lnsc,
            float* __restrict__ out) {
    extern __shared__ __half smem_h[];
    __half* Qs = smem_h;                 // [64][STH]
    __half* Ks = Qs + 64 * STH;          // [128][STH]
    __half* Vs = Ks + 128 * STH;         // [128][STH]
    __half* Ps = Vs + 128 * STH;         // [64][STH]
    float* sMq = (float*)(Ps + 64 * STH);  // [64]
    float* sn2 = sMq + 64;               // [64]
    float* sR  = sn2 + 64;               // [64]
    float* rrs = sR + 64;                // [4][64]
    float* rsm = rrs + 256;              // [4][64]
    float* rsq = rsm + 256;              // [4][64]

    int h    = blockIdx.y;
    int pair = blockIdx.x;
    int tid  = threadIdx.x;
    int wid  = tid >> 5, lane = tid & 31;
    int wy   = wid >> 2, wx = wid & 3;     // wy 0..1 (m), wx 0..3 (n)
    int g    = lane >> 2, tig = lane & 3;

    // per-lane ldmatrix.trans base address into Vs
    unsigned vsm = (unsigned)__cvta_generic_to_shared(Vs);
    {
        int sel = lane >> 3, l8 = lane & 7;
        vsm += (((sel & 1) * 8 + l8) * STH + wx * 32 + (sel >> 1) * 8) * 2;
    }

    const float qscale = 0.08838834764831845f;   // 1/sqrt(128)

    for (int qsel = 0; qsel < 2; ++qsel) {
        int qt  = qsel ? pair : (31 - pair);     // heavy block first
        int i0  = qt * 64;
        int njt = qt / 2 + 1;

        __syncthreads();  // prior epilogue done before smem reuse
        // load Q -> half (pre-scaled)
        for (int idx = tid; idx < 64 * 32; idx += 256) {
            int i = idx >> 5, c4 = (idx & 31) * 4;
            float4 t4 = *(const float4*)&q[(i0 + i) * E_DIM + h * DH + c4];
            __half2 h01 = __floats2half2_rn(t4.x * qscale, t4.y * qscale);
            __half2 h23 = __floats2half2_rn(t4.z * qscale, t4.w * qscale);
            uint2 u = make_uint2(*(unsigned*)&h01, *(unsigned*)&h23);
            *(uint2*)&Qs[i * STH + c4] = u;
        }
        if (tid < 64) {
            sMq[tid] = g_M[h][i0 + tid];
            sn2[tid] = g_n2[h][i0 + tid];
        }

        float Oa[2][4][4];
        #pragma unroll
        for (int mi = 0; mi < 2; ++mi)
            #pragma unroll
            for (int nt = 0; nt < 4; ++nt)
                #pragma unroll
                for (int c = 0; c < 4; ++c) Oa[mi][nt][c] = 0.f;
        float rs[2][2] = {{0.f, 0.f}, {0.f, 0.f}};

        for (int jt = 0; jt < njt; ++jt) {
            int j0 = jt * 128;
            __syncthreads();   // prior PV reads done; sMq visible
            float T = g_T[h][jt];
            for (int idx = tid; idx < 128 * 32; idx += 256) {
                int j = idx >> 5, c4 = (idx & 31) * 4;
                float e = g_E[h][j0 + j];
                float4 kt = *(const float4*)&k[(j0 + j) * E_DIM + h * DH + c4];
                __half2 k01 = __floats2half2_rn(kt.x * e, kt.y * e);
                __half2 k23 = __floats2half2_rn(kt.z * e, kt.w * e);
                *(uint2*)&Ks[j * STH + c4] = make_uint2(*(unsigned*)&k01, *(unsigned*)&k23);
                float4 vt = *(const float4*)&v[(j0 + j) * E_DIM + h * DH + c4];
                __half2 v01 = __floats2half2_rn(vt.x, vt.y);
                __half2 v23 = __floats2half2_rn(vt.z, vt.w);
                *(uint2*)&Vs[j * STH + c4] = make_uint2(*(unsigned*)&v01, *(unsigned*)&v23);
            }
            if (tid < 64) sR[tid] = __expf(T - sMq[tid]);
            __syncthreads();

            // ---- QK^T (f16 mma m16n8k16), warp tile m32 x n32 ----
            float acc[2][4][4];
            #pragma unroll
            for (int mi = 0; mi < 2; ++mi)
                #pragma unroll
                for (int nt = 0; nt < 4; ++nt)
                    #pragma unroll
                    for (int c = 0; c < 4; ++c) acc[mi][nt][c] = 0.f;

            #pragma unroll
            for (int ks = 0; ks < 8; ++ks) {
                int d0 = ks * 16;
                unsigned a[2][4], b[4][2];
                #pragma unroll
                for (int mi = 0; mi < 2; ++mi) {
                    int r0 = wy * 32 + mi * 16 + g;
                    a[mi][0] = *(const unsigned*)&Qs[r0 * STH + d0 + 2 * tig];
                    a[mi][1] = *(const unsigned*)&Qs[(r0 + 8) * STH + d0 + 2 * tig];
                    a[mi][2] = *(const unsigned*)&Qs[r0 * STH + d0 + 8 + 2 * tig];
                    a[mi][3] = *(const unsigned*)&Qs[(r0 + 8) * STH + d0 + 8 + 2 * tig];
                }
                #pragma unroll
                for (int nt = 0; nt < 4; ++nt) {
                    int jb = wx * 32 + nt * 8 + g;
                    b[nt][0] = *(const unsigned*)&Ks[jb * STH + d0 + 2 * tig];
                    b[nt][1] = *(const unsigned*)&Ks[jb * STH + d0 + 8 + 2 * tig];
                }
                #pragma unroll
                for (int mi = 0; mi < 2; ++mi)
                    #pragma unroll
                    for (int nt = 0; nt < 4; ++nt)
                        mma16(acc[mi][nt], a[mi], b[nt]);
            }

            // ---- apply R, mask, rowsum, stage P (half) ----
            bool last = (jt == njt - 1);
            #pragma unroll
            for (int mi = 0; mi < 2; ++mi) {
                int rl = wy * 32 + mi * 16 + g;
                float Rl = sR[rl], Rh = sR[rl + 8];
                int iglo = i0 + rl, ighi = iglo + 8;
                #pragma unroll
                for (int nt = 0; nt < 4; ++nt) {
                    int jc = wx * 32 + nt * 8 + 2 * tig;
                    int jg = j0 + jc;
                    float p0 = acc[mi][nt][0] * Rl;
                    float p1 = acc[mi][nt][1] * Rl;
                    float p2 = acc[mi][nt][2] * Rh;
                    float p3 = acc[mi][nt][3] * Rh;
                    if (last) {
                        if (jg     > iglo) p0 = 0.f;
                        if (jg + 1 > iglo) p1 = 0.f;
                        if (jg     > ighi) p2 = 0.f;
                        if (jg + 1 > ighi) p3 = 0.f;
                    }
                    rs[mi][0] += p0 + p1;
                    rs[mi][1] += p2 + p3;
                    *(__half2*)&Ps[rl * STH + jc]       = __floats2half2_rn(p0, p1);
                    *(__half2*)&Ps[(rl + 8) * STH + jc] = __floats2half2_rn(p2, p3);
                }
            }
            __syncthreads();

            // ---- P @ V (f16 mma), V B-frags via ldmatrix.trans ----
            #pragma unroll
            for (int ks = 0; ks < 8; ++ks) {
                int j8 = ks * 16;
                unsigned a[2][4], b[4][2];
                #pragma unroll
                for (int mi = 0; mi < 2; ++mi) {
                    int r0 = wy * 32 + mi * 16 + g;
                    a[mi][0] = *(const unsigned*)&Ps[r0 * STH + j8 + 2 * tig];
                    a[mi][1] = *(const unsigned*)&Ps[(r0 + 8) * STH + j8 + 2 * tig];
                    a[mi][2] = *(const unsigned*)&Ps[r0 * STH + j8 + 8 + 2 * tig];
                    a[mi][3] = *(const unsigned*)&Ps[(r0 + 8) * STH + j8 + 8 + 2 * tig];
                }
                #pragma unroll
                for (int p = 0; p < 2; ++p) {
                    unsigned r4[4];
                    ldsm4t(r4, vsm + (unsigned)((j8 * STH + p * 16) * 2));
                    b[2 * p][0]     = r4[0];
                    b[2 * p][1]     = r4[1];
                    b[2 * p + 1][0] = r4[2];
                    b[2 * p + 1][1] = r4[3];
                }
                #pragma unroll
                for (int mi = 0; mi < 2; ++mi)
                    #pragma unroll
                    for (int nt = 0; nt < 4; ++nt)
                        mma16(Oa[mi][nt], a[mi], b[nt]);
            }
        }

        // ---- epilogue: reduce rs / sum / sumsq, normalize, LN, store ----
        float sm1[2][2] = {{0.f,0.f},{0.f,0.f}};
        float sq1[2][2] = {{0.f,0.f},{0.f,0.f}};
        #pragma unroll
        for (int mi = 0; mi < 2; ++mi)
            #pragma unroll
            for (int nt = 0; nt < 4; ++nt) {
                sm1[mi][0] += Oa[mi][nt][0] + Oa[mi][nt][1];
                sq1[mi][0] += Oa[mi][nt][0] * Oa[mi][nt][0] + Oa[mi][nt][1] * Oa[mi][nt][1];
                sm1[mi][1] += Oa[mi][nt][2] + Oa[mi][nt][3];
                sq1[mi][1] += Oa[mi][nt][2] * Oa[mi][nt][2] + Oa[mi][nt][3] * Oa[mi][nt][3];
            }
        #pragma unroll
        for (int mi = 0; mi < 2; ++mi)
            #pragma unroll
            for (int c = 0; c < 2; ++c) {
                rs [mi][c] += __shfl_xor_sync(0xffffffffu, rs [mi][c], 1);
                rs [mi][c] += __shfl_xor_sync(0xffffffffu, rs [mi][c], 2);
                sm1[mi][c] += __shfl_xor_sync(0xffffffffu, sm1[mi][c], 1);
                sm1[mi][c] += __shfl_xor_sync(0xffffffffu, sm1[mi][c], 2);
                sq1[mi][c] += __shfl_xor_sync(0xffffffffu, sq1[mi][c], 1);
                sq1[mi][c] += __shfl_xor_sync(0xffffffffu, sq1[mi][c], 2);
            }
        if (tig == 0) {
            #pragma unroll
            for (int mi = 0; mi < 2; ++mi)
                #pragma unroll
                for (int c = 0; c < 2; ++c) {
                    int row = wy * 32 + mi * 16 + g + 8 * c;
                    rrs[wx * 64 + row] = rs [mi][c];
                    rsm[wx * 64 + row] = sm1[mi][c];
                    rsq[wx * 64 + row] = sq1[mi][c];
                }
        }
        __syncthreads();
        if (tid < 64) {
            float tot = rrs[tid] + rrs[64 + tid] + rrs[128 + tid] + rrs[192 + tid];
            float s1  = rsm[tid] + rsm[64 + tid] + rsm[128 + tid] + rsm[192 + tid];
            float s2  = rsq[tid] + rsq[64 + tid] + rsq[128 + tid] + rsq[192 + tid];
            float denom = fmaxf(fabsf(tot), sn2[tid]) + EPS_F;
            float invd  = 1.f / denom;
            float mean  = s1 * invd * (1.f / 128.f);
            float ex2   = s2 * invd * invd * (1.f / 128.f);
            float rstd  = rsqrtf(ex2 - mean * mean + EPS_F);
            sR [tid] = invd;
            sMq[tid] = mean;
            sn2[tid] = rstd;
        }
        __syncthreads();
        float2 gp[4];
        #pragma unroll
        for (int nt = 0; nt < 4; ++nt)
            gp[nt] = *(const float2*)&lnsc[h * DH + wx * 32 + nt * 8 + 2 * tig];
        #pragma unroll
        for (int mi = 0; mi < 2; ++mi)
            #pragma unroll
            for (int c = 0; c < 2; ++c) {
                int row = wy * 32 + mi * 16 + g + 8 * c;
                float invd = sR[row], mean = sMq[row], rstd = sn2[row];
                int grow = i0 + row;
                #pragma unroll
                for (int nt = 0; nt < 4; ++nt) {
                    float x0 = (Oa[mi][nt][2 * c]     * invd - mean) * rstd * gp[nt].x;
                    float x1 = (Oa[mi][nt][2 * c + 1] * invd - mean) * rstd * gp[nt].y;
                    *(float2*)&out[grow * E_DIM + h * DH + wx * 32 + nt * 8 + 2 * tig]
                        = make_float2(x0, x1);
                }
            }
    }
}

// =================================================================
extern "C" void kernel_launch(void* const* d_in, const int* in_sizes, int n_in,
                              void* d_out, int out_size) {
    const float* q    = (const float*)d_in[0];
    const float* k    = (const float*)d_in[1];
    const float* v    = (const float*)d_in[2];
    const float* Wi   = (const float*)d_in[3];
    const float* bi   = (const float*)d_in[4];
    const float* Wf   = (const float*)d_in[5];
    const float* bf   = (const float*)d_in[6];
    const float* lnsc = (const float*)d_in[7];
    float* out = (float*)d_out;

    const int gate_smem = 1024 * 18 * 4;                      // 73728 B
    const int attn_smem = 384 * STH * 2 + 960 * 4;            // 104448 + 3840 = 108288 B

    cudaFuncSetAttribute(gate_kernel, cudaFuncAttributeMaxDynamicSharedMemorySize, gate_smem);
    cudaFuncSetAttribute(attn_kernel, cudaFuncAttributeMaxDynamicSharedMemorySize, attn_smem);

    gate_kernel<<<dim3(128, 3), 256, gate_smem>>>(q, k, v, Wi, Wf);
    scan_kernel<<<8, 1024>>>(bi, bf);
    dim3 grid(16, NH);
    attn_kernel<<<grid, 256, attn_smem>>>(q, k, v, lnsc, out);
}